// round 9
// baseline (speedup 1.0000x reference)
#include <cuda_runtime.h>
#include <cuda_fp16.h>

// ============================================================================
// RFEncoder: 2-layer hetero GATv2 (2 relations, 2 heads, HID=64)
//
// R8 (fix of R7): redux.sync.add.f32 does NOT exist on sm_103 -> back to the
// 4-level shuffle tree for the per-head (16-lane) reduction. Keep the R7
// instruction-cut algebra, which is the actual win:
//   - leaky(v) = 0.6v + 0.4|v|  ->  score = linear(precomputed) + 0.4*att.|v|
//   - layer-1: linear part = q.x*A0 + q.y*A1 + C (warp-prologue scalars)
//   - layer-2: 0.6*att.xl per node precomputed in the transform epilogue,
//              0.6*att.xr per node in the pull prologue
// Keeps: shift-free softmax, CSR pull, numerator linearity (layer 1),
// fp16 gathered operand (layer 2), __expf, 4-edge groups.
// ============================================================================

#define NMAX 100000
#define EMAX 800000
#define HD   128   // HEADS * HID

__device__ __half g_xlh[2][NMAX * HD];   // layer-2 xl, fp16 (gathered operand)
__device__ float  g_xr [2][NMAX * HD];   // layer-2 xr, fp32 (per-node read)
__device__ float  g_asc[2][NMAX * 2];    // 0.6 * att . xl  per node per head
__device__ float  g_h  [NMAX * 64];
__device__ int    g_rowptr[2][NMAX + 1];
__device__ int    g_cursor[2][NMAX];     // zeroed at load; re-zeroed by tail
__device__ int    g_csrc  [2][EMAX];

// Reduction over each 16-lane half (per attention head): shuffle tree.
__device__ __forceinline__ float redux16(float v) {
    v += __shfl_xor_sync(0xffffffffu, v, 8);
    v += __shfl_xor_sync(0xffffffffu, v, 4);
    v += __shfl_xor_sync(0xffffffffu, v, 2);
    v += __shfl_xor_sync(0xffffffffu, v, 1);
    return v;
}

// ---------------------------------------------------------------------------
__global__ void zero2_kernel(int* __restrict__ cur, int n) {
    int i = blockIdx.x * blockDim.x + threadIdx.x;
    if (i < n) { cur[i] = 0; cur[NMAX + i] = 0; }
}

__global__ void hist2_kernel(const int* __restrict__ dst0,
                             const int* __restrict__ dst1,
                             int* __restrict__ cur, int E) {
    int e = blockIdx.x * blockDim.x + threadIdx.x;
    if (e >= E) return;
    const int* d = blockIdx.y ? dst1 : dst0;
    atomicAdd(&cur[blockIdx.y * NMAX + d[e]], 1);
}

__global__ void scan2_kernel(int* __restrict__ cursor, int* __restrict__ rowptr,
                             int n) {
    __shared__ int part[1024];
    int r = blockIdx.x;
    int* cur = cursor + r * NMAX;
    int* rp  = rowptr + r * (NMAX + 1);
    int t = threadIdx.x;
    int chunk = (n + 1023) / 1024;
    int lo = t * chunk;
    int hi = lo + chunk; if (hi > n) hi = n;

    int s = 0;
    for (int i = lo; i < hi; i++) s += cur[i];
    part[t] = s;
    __syncthreads();
    for (int d = 1; d < 1024; d <<= 1) {
        int v = (t >= d) ? part[t - d] : 0;
        __syncthreads();
        part[t] += v;
        __syncthreads();
    }
    int off = (t == 0) ? 0 : part[t - 1];
    for (int i = lo; i < hi; i++) {
        int dv = cur[i];
        rp[i] = off;
        cur[i] = off;
        off += dv;
    }
    if (hi == n) rp[n] = off;
}

__global__ void scatter2_kernel(const int* __restrict__ ea,
                                const int* __restrict__ er,
                                int* __restrict__ cursor,
                                int* __restrict__ csrc, int E) {
    int e = blockIdx.x * blockDim.x + threadIdx.x;
    if (e >= E) return;
    int r = blockIdx.y;
    const int* edges = r ? er : ea;
    int pos = atomicAdd(&cursor[r * NMAX + edges[E + e]], 1);
    csrc[r * EMAX + pos] = edges[e];
}

// ---------------------------------------------------------------------------
// Layer 1, fully fused. Score via abs-decomposition:
//   score = q.x*A0 + q.y*A1 + C + sum_c (0.4 att_c)|v_c|
// with A0 = 0.6 sum att*wl0, A1 = 0.6 sum att*wl1, C = 0.6 sum att*base.
__global__ void __launch_bounds__(128, 6)
layer1_fused_kernel(const int* __restrict__ rowptr,
                    const int* __restrict__ csrc,
                    const float* __restrict__ x,      // [n][2]
                    const float* __restrict__ Wl,     // [2][2][128]
                    const float* __restrict__ bl,     // [2][128]
                    const float* __restrict__ Wr,
                    const float* __restrict__ br,
                    const float* __restrict__ att,    // [2][128]
                    const float* __restrict__ bias,   // [2][64]
                    float* __restrict__ h, int n) {
    const unsigned F = 0xffffffffu;
    int node = (blockIdx.x * blockDim.x + threadIdx.x) >> 5;
    if (node >= n) return;
    int lane = threadIdx.x & 31;

    const float2 xd = ((const float2*)x)[node];
    float4 outv = make_float4(0.f, 0.f, 0.f, 0.f);

#pragma unroll 1
    for (int r = 0; r < 2; r++) {
        const float4 wl0 = *(const float4*)&Wl[r * 256 + lane * 4];
        const float4 wl1 = *(const float4*)&Wl[r * 256 + HD + lane * 4];
        const float4 blv = *(const float4*)&bl[r * HD + lane * 4];
        const float4 a4  = *(const float4*)&att[r * HD + lane * 4];

        // base = bl + xr[d]
        float4 base;
        {
            const float4 wr0 = *(const float4*)&Wr[r * 256 + lane * 4];
            const float4 wr1 = *(const float4*)&Wr[r * 256 + HD + lane * 4];
            const float4 brv = *(const float4*)&br[r * HD + lane * 4];
            base.x = fmaf(xd.y, wr1.x, fmaf(xd.x, wr0.x, brv.x)) + blv.x;
            base.y = fmaf(xd.y, wr1.y, fmaf(xd.x, wr0.y, brv.y)) + blv.y;
            base.z = fmaf(xd.y, wr1.z, fmaf(xd.x, wr0.z, brv.z)) + blv.z;
            base.w = fmaf(xd.y, wr1.w, fmaf(xd.x, wr0.w, brv.w)) + blv.w;
        }

        // linear score coefficients (per head, uniform in each 16-lane group)
        float A0, A1, C;
        {
            float p0 = a4.x * wl0.x + a4.y * wl0.y + a4.z * wl0.z + a4.w * wl0.w;
            float p1 = a4.x * wl1.x + a4.y * wl1.y + a4.z * wl1.z + a4.w * wl1.w;
            float pc = a4.x * base.x + a4.y * base.y + a4.z * base.z + a4.w * base.w;
            A0 = 0.6f * redux16(p0);
            A1 = 0.6f * redux16(p1);
            C  = 0.6f * redux16(pc);
        }
        const float4 a4s = make_float4(0.4f * a4.x, 0.4f * a4.y,
                                       0.4f * a4.z, 0.4f * a4.w);

        const int* rp = rowptr + r * (NMAX + 1);
        const int* cs = csrc   + r * EMAX;
        int beg = rp[node];
        int end = rp[node + 1];

        float S0 = 0.f, S1 = 0.f, den = 0.f;

        for (int bse = beg; bse < end; bse += 32) {
            int cnt = end - bse; if (cnt > 32) cnt = 32;
            int ld = bse + lane; if (ld >= end) ld = end - 1;
            int sv = cs[ld];

            for (int j = 0; j < cnt; j += 4) {
                int i1 = (j + 1 < cnt) ? j + 1 : j;
                int i2 = (j + 2 < cnt) ? j + 2 : j;
                int i3 = (j + 3 < cnt) ? j + 3 : j;
                int s0 = __shfl_sync(F, sv, j);
                int s1 = __shfl_sync(F, sv, i1);
                int s2 = __shfl_sync(F, sv, i2);
                int s3 = __shfl_sync(F, sv, i3);

                float2 q0 = ((const float2*)x)[s0];
                float2 q1 = ((const float2*)x)[s1];
                float2 q2 = ((const float2*)x)[s2];
                float2 q3 = ((const float2*)x)[s3];

                float p0, p1, p2, p3;
#define ABSPART(p, q) { \
    float v0 = fmaf(q.y, wl1.x, fmaf(q.x, wl0.x, base.x)); \
    float v1 = fmaf(q.y, wl1.y, fmaf(q.x, wl0.y, base.y)); \
    float v2 = fmaf(q.y, wl1.z, fmaf(q.x, wl0.z, base.z)); \
    float v3 = fmaf(q.y, wl1.w, fmaf(q.x, wl0.w, base.w)); \
    float pA = a4s.x * fabsf(v0); \
    float pB = a4s.y * fabsf(v1); \
    pA = fmaf(a4s.z, fabsf(v2), pA); \
    pB = fmaf(a4s.w, fabsf(v3), pB); \
    p = pA + pB; }
                ABSPART(p0, q0) ABSPART(p1, q1) ABSPART(p2, q2) ABSPART(p3, q3)
#undef ABSPART

#pragma unroll
                for (int d = 8; d >= 1; d >>= 1) {
                    p0 += __shfl_xor_sync(F, p0, d);
                    p1 += __shfl_xor_sync(F, p1, d);
                    p2 += __shfl_xor_sync(F, p2, d);
                    p3 += __shfl_xor_sync(F, p3, d);
                }

                float l0 = fmaf(q0.x, A0, fmaf(q0.y, A1, C));
                float l1 = fmaf(q1.x, A0, fmaf(q1.y, A1, C));
                float l2 = fmaf(q2.x, A0, fmaf(q2.y, A1, C));
                float l3 = fmaf(q3.x, A0, fmaf(q3.y, A1, C));

                float e0 = __expf(p0 + l0);
                float e1 = (j + 1 < cnt) ? __expf(p1 + l1) : 0.f;
                float e2 = (j + 2 < cnt) ? __expf(p2 + l2) : 0.f;
                float e3 = (j + 3 < cnt) ? __expf(p3 + l3) : 0.f;

                S0 = fmaf(e0, q0.x, S0); S1 = fmaf(e0, q0.y, S1);
                S0 = fmaf(e1, q1.x, S0); S1 = fmaf(e1, q1.y, S1);
                S0 = fmaf(e2, q2.x, S0); S1 = fmaf(e2, q2.y, S1);
                S0 = fmaf(e3, q3.x, S0); S1 = fmaf(e3, q3.y, S1);
                den += e0 + e1 + e2 + e3;
            }
        }

        float inv = 0.25f / (den + 1e-16f);
        outv.x = fmaf(fmaf(S1, wl1.x, fmaf(S0, wl0.x, den * blv.x)), inv, outv.x);
        outv.y = fmaf(fmaf(S1, wl1.y, fmaf(S0, wl0.y, den * blv.y)), inv, outv.y);
        outv.z = fmaf(fmaf(S1, wl1.z, fmaf(S0, wl0.z, den * blv.z)), inv, outv.z);
        outv.w = fmaf(fmaf(S1, wl1.w, fmaf(S0, wl0.w, den * blv.w)), inv, outv.w);
    }

    outv.x += __shfl_xor_sync(F, outv.x, 16);
    outv.y += __shfl_xor_sync(F, outv.y, 16);
    outv.z += __shfl_xor_sync(F, outv.z, 16);
    outv.w += __shfl_xor_sync(F, outv.w, 16);

    if (lane < 16) {
        int c = lane * 4;
        outv.x += 0.5f * (bias[c + 0] + bias[64 + c + 0]);
        outv.y += 0.5f * (bias[c + 1] + bias[64 + c + 1]);
        outv.z += 0.5f * (bias[c + 2] + bias[64 + c + 2]);
        outv.w += 0.5f * (bias[c + 3] + bias[64 + c + 3]);
        outv.x = outv.x > 0.f ? outv.x : 0.f;
        outv.y = outv.y > 0.f ? outv.y : 0.f;
        outv.z = outv.z > 0.f ? outv.z : 0.f;
        outv.w = outv.w > 0.f ? outv.w : 0.f;
        *(float4*)&h[(size_t)node * 64 + c] = outv;
    }
}

// ---------------------------------------------------------------------------
// Layer-2 transforms: 4 GEMMs via grid.y. xl -> fp16 (+ per-node 0.6*att.xl),
// xr -> fp32.
__global__ void __launch_bounds__(128)
transform64_all_kernel(const float* __restrict__ X,
                       const float* __restrict__ Wl,
                       const float* __restrict__ bl,
                       const float* __restrict__ Wr,
                       const float* __restrict__ br,
                       const float* __restrict__ att,   // [2][128]
                       __half* __restrict__ xlh,        // [2][NMAX*HD]
                       float* __restrict__ xrf,         // [2][NMAX*HD]
                       float* __restrict__ asc,         // [2][NMAX*2]
                       int n) {
    __shared__ float sW[64 * 128];
    __shared__ float sX[32 * 68];

    int y = blockIdx.y;
    int r = y >> 1;
    bool is_xl = (y & 1) == 0;
    const float* W = is_xl ? (Wl + r * 64 * HD) : (Wr + r * 64 * HD);
    const float* b = is_xl ? (bl + r * HD)      : (br + r * HD);

    int tx = threadIdx.x;
    for (int idx = tx * 4; idx < 64 * 128; idx += 128 * 4)
        *(float4*)&sW[idx] = *(const float4*)&W[idx];

    int node0 = blockIdx.x * 32;
    for (int idx = tx; idx < 512; idx += 128) {
        int rr = idx >> 4;
        int c4 = idx & 15;
        float4 v = make_float4(0.f, 0.f, 0.f, 0.f);
        if (node0 + rr < n)
            v = *(const float4*)&X[(size_t)(node0 + rr) * 64 + c4 * 4];
        *(float4*)&sX[rr * 68 + c4 * 4] = v;
    }
    __syncthreads();

    int cg = tx & 15;
    int ng = tx >> 4;

    float acc[4][8];
#pragma unroll
    for (int m = 0; m < 4; m++)
#pragma unroll
        for (int j = 0; j < 8; j++) acc[m][j] = b[cg * 8 + j];

    for (int k = 0; k < 64; k += 4) {
        float4 xv[4];
#pragma unroll
        for (int m = 0; m < 4; m++)
            xv[m] = *(const float4*)&sX[(ng * 4 + m) * 68 + k];
#pragma unroll
        for (int kk = 0; kk < 4; kk++) {
            float4 w0 = *(const float4*)&sW[(k + kk) * 128 + cg * 8];
            float4 w1 = *(const float4*)&sW[(k + kk) * 128 + cg * 8 + 4];
#pragma unroll
            for (int m = 0; m < 4; m++) {
                float xs = (kk == 0) ? xv[m].x : (kk == 1) ? xv[m].y
                         : (kk == 2) ? xv[m].z : xv[m].w;
                acc[m][0] = fmaf(xs, w0.x, acc[m][0]);
                acc[m][1] = fmaf(xs, w0.y, acc[m][1]);
                acc[m][2] = fmaf(xs, w0.z, acc[m][2]);
                acc[m][3] = fmaf(xs, w0.w, acc[m][3]);
                acc[m][4] = fmaf(xs, w1.x, acc[m][4]);
                acc[m][5] = fmaf(xs, w1.y, acc[m][5]);
                acc[m][6] = fmaf(xs, w1.z, acc[m][6]);
                acc[m][7] = fmaf(xs, w1.w, acc[m][7]);
            }
        }
    }

    if (is_xl) {
        __half* Y = xlh + (size_t)r * NMAX * HD;
        const float* attc = att + r * HD + cg * 8;
        float a0 = attc[0], a1 = attc[1], a2 = attc[2], a3 = attc[3];
        float a4_ = attc[4], a5 = attc[5], a6 = attc[6], a7 = attc[7];
#pragma unroll
        for (int m = 0; m < 4; m++) {
            int node = node0 + ng * 4 + m;
            // per-node per-head linear term: 0.6 * sum att_c * xl_c
            float part = a0 * acc[m][0] + a1 * acc[m][1]
                       + a2 * acc[m][2] + a3 * acc[m][3]
                       + a4_ * acc[m][4] + a5 * acc[m][5]
                       + a6 * acc[m][6] + a7 * acc[m][7];
#pragma unroll
            for (int d = 1; d <= 4; d <<= 1)
                part += __shfl_xor_sync(0xffffffffu, part, d);
            if (node < n) {
                if ((cg & 7) == 0)
                    asc[(size_t)r * NMAX * 2 + node * 2 + (cg >> 3)] = 0.6f * part;
                __half2 p0 = __float22half2_rn(make_float2(acc[m][0], acc[m][1]));
                __half2 p1 = __float22half2_rn(make_float2(acc[m][2], acc[m][3]));
                __half2 p2 = __float22half2_rn(make_float2(acc[m][4], acc[m][5]));
                __half2 p3 = __float22half2_rn(make_float2(acc[m][6], acc[m][7]));
                uint4 pk;
                pk.x = *(unsigned*)&p0; pk.y = *(unsigned*)&p1;
                pk.z = *(unsigned*)&p2; pk.w = *(unsigned*)&p3;
                *(uint4*)&Y[(size_t)node * HD + cg * 8] = pk;
            }
        }
    } else {
        float* Y = xrf + (size_t)r * NMAX * HD;
#pragma unroll
        for (int m = 0; m < 4; m++) {
            int node = node0 + ng * 4 + m;
            if (node < n) {
                *(float4*)&Y[(size_t)node * HD + cg * 8] =
                    make_float4(acc[m][0], acc[m][1], acc[m][2], acc[m][3]);
                *(float4*)&Y[(size_t)node * HD + cg * 8 + 4] =
                    make_float4(acc[m][4], acc[m][5], acc[m][6], acc[m][7]);
            }
        }
    }
}

// ---------------------------------------------------------------------------
// Layer-2 fused pull: score = A6[s] + B6[d] + sum(0.4 att|a+xr|).
__global__ void __launch_bounds__(128, 6)
layer2_fused_kernel(const int* __restrict__ rowptr,
                    const int* __restrict__ csrc,
                    const __half* __restrict__ xlh,   // [2][NMAX*HD]
                    const float* __restrict__ xrf,    // [2][NMAX*HD]
                    const float* __restrict__ asc,    // [2][NMAX*2]
                    const float* __restrict__ att,
                    const float* __restrict__ bias,
                    float* __restrict__ out, int n) {
    const unsigned F = 0xffffffffu;
    int node = (blockIdx.x * blockDim.x + threadIdx.x) >> 5;
    if (node >= n) return;
    int lane = threadIdx.x & 31;

    float4 outv = make_float4(0.f, 0.f, 0.f, 0.f);

#pragma unroll 1
    for (int r = 0; r < 2; r++) {
        const __half*  xl  = xlh + (size_t)r * NMAX * HD;
        const float*   xr  = xrf + (size_t)r * NMAX * HD;
        const float2*  asr = (const float2*)(asc + (size_t)r * NMAX * 2);
        const float4 a4  = *(const float4*)&att[r * HD + lane * 4];
        const float4 xrv = *(const float4*)&xr[(size_t)node * HD + lane * 4];

        // B6 = 0.6 * sum att*xr per head (uniform in each 16-lane group)
        float B6;
        {
            float pb = a4.x * xrv.x + a4.y * xrv.y + a4.z * xrv.z + a4.w * xrv.w;
            B6 = 0.6f * redux16(pb);
        }
        const float4 a4s = make_float4(0.4f * a4.x, 0.4f * a4.y,
                                       0.4f * a4.z, 0.4f * a4.w);

        const int* rp = rowptr + r * (NMAX + 1);
        const int* cs = csrc   + r * EMAX;
        int beg = rp[node];
        int end = rp[node + 1];

        float4 ns = make_float4(0.f, 0.f, 0.f, 0.f);
        float den = 0.f;

        for (int bse = beg; bse < end; bse += 32) {
            int cnt = end - bse; if (cnt > 32) cnt = 32;
            int ld = bse + lane; if (ld >= end) ld = end - 1;
            int sv = cs[ld];

            for (int j = 0; j < cnt; j += 4) {
                int i1 = (j + 1 < cnt) ? j + 1 : j;
                int i2 = (j + 2 < cnt) ? j + 2 : j;
                int i3 = (j + 3 < cnt) ? j + 3 : j;
                int s0 = __shfl_sync(F, sv, j);
                int s1 = __shfl_sync(F, sv, i1);
                int s2 = __shfl_sync(F, sv, i2);
                int s3 = __shfl_sync(F, sv, i3);

                // 8 B fp16 gathers + per-source linear term
                uint2 r0 = *(const uint2*)&xl[(size_t)s0 * HD + lane * 4];
                uint2 r1 = *(const uint2*)&xl[(size_t)s1 * HD + lane * 4];
                uint2 r2 = *(const uint2*)&xl[(size_t)s2 * HD + lane * 4];
                uint2 r3 = *(const uint2*)&xl[(size_t)s3 * HD + lane * 4];
                float2 A0 = asr[s0];
                float2 A1 = asr[s1];
                float2 A2 = asr[s2];
                float2 A3 = asr[s3];

                float4 a0, a1, a2, a3;
#define UNPACK(a, rr) { \
    float2 lo = __half22float2(*(__half2*)&rr.x); \
    float2 hi = __half22float2(*(__half2*)&rr.y); \
    a = make_float4(lo.x, lo.y, hi.x, hi.y); }
                UNPACK(a0, r0) UNPACK(a1, r1) UNPACK(a2, r2) UNPACK(a3, r3)
#undef UNPACK

                float p0, p1, p2, p3;
#define ABSPART(p, a) { \
    float v0 = a.x + xrv.x; \
    float v1 = a.y + xrv.y; \
    float v2 = a.z + xrv.z; \
    float v3 = a.w + xrv.w; \
    float pA = a4s.x * fabsf(v0); \
    float pB = a4s.y * fabsf(v1); \
    pA = fmaf(a4s.z, fabsf(v2), pA); \
    pB = fmaf(a4s.w, fabsf(v3), pB); \
    p = pA + pB; }
                ABSPART(p0, a0) ABSPART(p1, a1) ABSPART(p2, a2) ABSPART(p3, a3)
#undef ABSPART

#pragma unroll
                for (int d = 8; d >= 1; d >>= 1) {
                    p0 += __shfl_xor_sync(F, p0, d);
                    p1 += __shfl_xor_sync(F, p1, d);
                    p2 += __shfl_xor_sync(F, p2, d);
                    p3 += __shfl_xor_sync(F, p3, d);
                }

                bool hi = lane >= 16;
                float l0 = (hi ? A0.y : A0.x) + B6;
                float l1 = (hi ? A1.y : A1.x) + B6;
                float l2 = (hi ? A2.y : A2.x) + B6;
                float l3 = (hi ? A3.y : A3.x) + B6;

                float e0 = __expf(p0 + l0);
                float e1 = (j + 1 < cnt) ? __expf(p1 + l1) : 0.f;
                float e2 = (j + 2 < cnt) ? __expf(p2 + l2) : 0.f;
                float e3 = (j + 3 < cnt) ? __expf(p3 + l3) : 0.f;

                ns.x = fmaf(e0, a0.x, ns.x); ns.y = fmaf(e0, a0.y, ns.y);
                ns.z = fmaf(e0, a0.z, ns.z); ns.w = fmaf(e0, a0.w, ns.w);
                ns.x = fmaf(e1, a1.x, ns.x); ns.y = fmaf(e1, a1.y, ns.y);
                ns.z = fmaf(e1, a1.z, ns.z); ns.w = fmaf(e1, a1.w, ns.w);
                ns.x = fmaf(e2, a2.x, ns.x); ns.y = fmaf(e2, a2.y, ns.y);
                ns.z = fmaf(e2, a2.z, ns.z); ns.w = fmaf(e2, a2.w, ns.w);
                ns.x = fmaf(e3, a3.x, ns.x); ns.y = fmaf(e3, a3.y, ns.y);
                ns.z = fmaf(e3, a3.z, ns.z); ns.w = fmaf(e3, a3.w, ns.w);
                den += e0 + e1 + e2 + e3;
            }
        }

        float inv = 0.25f / (den + 1e-16f);
        outv.x = fmaf(ns.x, inv, outv.x);
        outv.y = fmaf(ns.y, inv, outv.y);
        outv.z = fmaf(ns.z, inv, outv.z);
        outv.w = fmaf(ns.w, inv, outv.w);
    }

    outv.x += __shfl_xor_sync(F, outv.x, 16);
    outv.y += __shfl_xor_sync(F, outv.y, 16);
    outv.z += __shfl_xor_sync(F, outv.z, 16);
    outv.w += __shfl_xor_sync(F, outv.w, 16);

    if (lane < 16) {
        int c = lane * 4;
        outv.x += 0.5f * (bias[c + 0] + bias[64 + c + 0]);
        outv.y += 0.5f * (bias[c + 1] + bias[64 + c + 1]);
        outv.z += 0.5f * (bias[c + 2] + bias[64 + c + 2]);
        outv.w += 0.5f * (bias[c + 3] + bias[64 + c + 3]);
        *(float4*)&out[(size_t)node * 64 + c] = outv;
    }
}

// ---------------------------------------------------------------------------
extern "C" void kernel_launch(void* const* d_in, const int* in_sizes, int n_in,
                              void* d_out, int out_size) {
    const float* x       = (const float*)d_in[0];
    const int*   e_adj   = (const int*)  d_in[1];
    const int*   e_ray   = (const int*)  d_in[2];
    const float* l1_Wl   = (const float*)d_in[3];
    const float* l1_bl   = (const float*)d_in[4];
    const float* l1_Wr   = (const float*)d_in[5];
    const float* l1_br   = (const float*)d_in[6];
    const float* l1_att  = (const float*)d_in[7];
    const float* l1_bias = (const float*)d_in[8];
    const float* l2_Wl   = (const float*)d_in[9];
    const float* l2_bl   = (const float*)d_in[10];
    const float* l2_Wr   = (const float*)d_in[11];
    const float* l2_br   = (const float*)d_in[12];
    const float* l2_att  = (const float*)d_in[13];
    const float* l2_bias = (const float*)d_in[14];

    const int N = in_sizes[0] / 2;
    const int E = in_sizes[1] / 2;

    __half* xlh; float *xrf, *ascp, *h;
    int *rowptr, *cursor, *csrc;
    cudaGetSymbolAddress((void**)&xlh,    g_xlh);
    cudaGetSymbolAddress((void**)&xrf,    g_xr);
    cudaGetSymbolAddress((void**)&ascp,   g_asc);
    cudaGetSymbolAddress((void**)&h,      g_h);
    cudaGetSymbolAddress((void**)&rowptr, g_rowptr);
    cudaGetSymbolAddress((void**)&cursor, g_cursor);
    cudaGetSymbolAddress((void**)&csrc,   g_csrc);

    const int ZB = 256;
    const int EB = (E + ZB - 1) / ZB;
    const int PULL_BLOCKS = (N + 3) / 4;

    // ----- CSR build (cursors pre-zeroed: load-time init + tail kernel) -----
    {
        dim3 g(EB, 2);
        hist2_kernel<<<g, ZB>>>(e_adj + E, e_ray + E, cursor, E);
    }
    scan2_kernel<<<2, 1024>>>(cursor, rowptr, N);
    {
        dim3 g(EB, 2);
        scatter2_kernel<<<g, ZB>>>(e_adj, e_ray, cursor, csrc, E);
    }

    // ----- Layer 1 (launch #4 -> ncu capture slot) -----
    layer1_fused_kernel<<<PULL_BLOCKS, 128>>>(
        rowptr, csrc, x, l1_Wl, l1_bl, l1_Wr, l1_br, l1_att, l1_bias, h, N);

    // ----- Layer 2 -----
    {
        dim3 g((N + 31) / 32, 4);
        transform64_all_kernel<<<g, 128>>>(h, l2_Wl, l2_bl, l2_Wr, l2_br,
                                           l2_att, xlh, xrf, ascp, N);
    }
    layer2_fused_kernel<<<PULL_BLOCKS, 128>>>(
        rowptr, csrc, xlh, xrf, ascp, l2_att, l2_bias, (float*)d_out, N);

    // ----- Tail: re-zero cursors for the next call -----
    zero2_kernel<<<(N + ZB - 1) / ZB, ZB>>>(cursor, N);
}

// round 10
// speedup vs baseline: 1.0898x; 1.0898x over previous
#include <cuda_runtime.h>
#include <cuda_fp16.h>

// ============================================================================
// RFEncoder: 2-layer hetero GATv2 (2 relations, 2 heads, HID=64)
//
// R9: revert R8's abs-decomposition (it removed latency-hiding filler and
// regressed). Back to the proven 719.6us structure, with ONE change:
// __launch_bounds__(128, 8) on both pull kernels (regs 72 -> 64) to lift
// occupancy 37.7% -> ~50% and close the 24% idle-issue gap seen in ncu.
// Keeps: shift-free softmax, CSR pull, numerator linearity (layer 1),
// fp16 gathered operand (layer 2), __expf, 4-edge groups, launch order with
// layer1_fused at ncu capture slot 4.
// ============================================================================

#define NMAX 100000
#define EMAX 800000
#define HD   128   // HEADS * HID

__device__ __half g_xlh[2][NMAX * HD];   // layer-2 xl, fp16 (gathered operand)
__device__ float  g_xr [2][NMAX * HD];   // layer-2 xr, fp32 (per-node read)
__device__ float  g_h  [NMAX * 64];
__device__ int    g_rowptr[2][NMAX + 1];
__device__ int    g_cursor[2][NMAX];     // zeroed at load; re-zeroed by tail
__device__ int    g_csrc  [2][EMAX];

// ---------------------------------------------------------------------------
__global__ void zero2_kernel(int* __restrict__ cur, int n) {
    int i = blockIdx.x * blockDim.x + threadIdx.x;
    if (i < n) { cur[i] = 0; cur[NMAX + i] = 0; }
}

__global__ void hist2_kernel(const int* __restrict__ dst0,
                             const int* __restrict__ dst1,
                             int* __restrict__ cur, int E) {
    int e = blockIdx.x * blockDim.x + threadIdx.x;
    if (e >= E) return;
    const int* d = blockIdx.y ? dst1 : dst0;
    atomicAdd(&cur[blockIdx.y * NMAX + d[e]], 1);
}

__global__ void scan2_kernel(int* __restrict__ cursor, int* __restrict__ rowptr,
                             int n) {
    __shared__ int part[1024];
    int r = blockIdx.x;
    int* cur = cursor + r * NMAX;
    int* rp  = rowptr + r * (NMAX + 1);
    int t = threadIdx.x;
    int chunk = (n + 1023) / 1024;
    int lo = t * chunk;
    int hi = lo + chunk; if (hi > n) hi = n;

    int s = 0;
    for (int i = lo; i < hi; i++) s += cur[i];
    part[t] = s;
    __syncthreads();
    for (int d = 1; d < 1024; d <<= 1) {
        int v = (t >= d) ? part[t - d] : 0;
        __syncthreads();
        part[t] += v;
        __syncthreads();
    }
    int off = (t == 0) ? 0 : part[t - 1];
    for (int i = lo; i < hi; i++) {
        int dv = cur[i];
        rp[i] = off;
        cur[i] = off;
        off += dv;
    }
    if (hi == n) rp[n] = off;
}

__global__ void scatter2_kernel(const int* __restrict__ ea,
                                const int* __restrict__ er,
                                int* __restrict__ cursor,
                                int* __restrict__ csrc, int E) {
    int e = blockIdx.x * blockDim.x + threadIdx.x;
    if (e >= E) return;
    int r = blockIdx.y;
    const int* edges = r ? er : ea;
    int pos = atomicAdd(&cursor[r * NMAX + edges[E + e]], 1);
    csrc[r * EMAX + pos] = edges[e];
}

// ---------------------------------------------------------------------------
// Layer 1, fully fused (numerator linearity; 8 B gathers of x[s]).
__global__ void __launch_bounds__(128, 8)
layer1_fused_kernel(const int* __restrict__ rowptr,
                    const int* __restrict__ csrc,
                    const float* __restrict__ x,      // [n][2]
                    const float* __restrict__ Wl,     // [2][2][128]
                    const float* __restrict__ bl,     // [2][128]
                    const float* __restrict__ Wr,
                    const float* __restrict__ br,
                    const float* __restrict__ att,    // [2][128]
                    const float* __restrict__ bias,   // [2][64]
                    float* __restrict__ h, int n) {
    const unsigned F = 0xffffffffu;
    int node = (blockIdx.x * blockDim.x + threadIdx.x) >> 5;
    if (node >= n) return;
    int lane = threadIdx.x & 31;

    const float2 xd = ((const float2*)x)[node];
    float4 outv = make_float4(0.f, 0.f, 0.f, 0.f);

#pragma unroll 1
    for (int r = 0; r < 2; r++) {
        const float4 wl0 = *(const float4*)&Wl[r * 256 + lane * 4];
        const float4 wl1 = *(const float4*)&Wl[r * 256 + HD + lane * 4];
        const float4 blv = *(const float4*)&bl[r * HD + lane * 4];
        const float4 a4  = *(const float4*)&att[r * HD + lane * 4];

        // base = bl + xr[d]
        float4 base;
        {
            const float4 wr0 = *(const float4*)&Wr[r * 256 + lane * 4];
            const float4 wr1 = *(const float4*)&Wr[r * 256 + HD + lane * 4];
            const float4 brv = *(const float4*)&br[r * HD + lane * 4];
            base.x = fmaf(xd.y, wr1.x, fmaf(xd.x, wr0.x, brv.x)) + blv.x;
            base.y = fmaf(xd.y, wr1.y, fmaf(xd.x, wr0.y, brv.y)) + blv.y;
            base.z = fmaf(xd.y, wr1.z, fmaf(xd.x, wr0.z, brv.z)) + blv.z;
            base.w = fmaf(xd.y, wr1.w, fmaf(xd.x, wr0.w, brv.w)) + blv.w;
        }

        const int* rp = rowptr + r * (NMAX + 1);
        const int* cs = csrc   + r * EMAX;
        int beg = rp[node];
        int end = rp[node + 1];

        float S0 = 0.f, S1 = 0.f, den = 0.f;

        for (int bse = beg; bse < end; bse += 32) {
            int cnt = end - bse; if (cnt > 32) cnt = 32;
            int ld = bse + lane; if (ld >= end) ld = end - 1;
            int sv = cs[ld];

            for (int j = 0; j < cnt; j += 4) {
                int i1 = (j + 1 < cnt) ? j + 1 : j;
                int i2 = (j + 2 < cnt) ? j + 2 : j;
                int i3 = (j + 3 < cnt) ? j + 3 : j;
                int s0 = __shfl_sync(F, sv, j);
                int s1 = __shfl_sync(F, sv, i1);
                int s2 = __shfl_sync(F, sv, i2);
                int s3 = __shfl_sync(F, sv, i3);

                float2 q0 = ((const float2*)x)[s0];
                float2 q1 = ((const float2*)x)[s1];
                float2 q2 = ((const float2*)x)[s2];
                float2 q3 = ((const float2*)x)[s3];

                float sc0, sc1, sc2, sc3;
#define SCORE1(sc, q) { \
    float v0 = fmaf(q.y, wl1.x, fmaf(q.x, wl0.x, base.x)); \
    float v1 = fmaf(q.y, wl1.y, fmaf(q.x, wl0.y, base.y)); \
    float v2 = fmaf(q.y, wl1.z, fmaf(q.x, wl0.z, base.z)); \
    float v3 = fmaf(q.y, wl1.w, fmaf(q.x, wl0.w, base.w)); \
    v0 = v0 > 0.f ? v0 : 0.2f * v0; \
    v1 = v1 > 0.f ? v1 : 0.2f * v1; \
    v2 = v2 > 0.f ? v2 : 0.2f * v2; \
    v3 = v3 > 0.f ? v3 : 0.2f * v3; \
    float pA = v0 * a4.x; \
    float pB = v1 * a4.y; \
    pA = fmaf(v2, a4.z, pA); \
    pB = fmaf(v3, a4.w, pB); \
    sc = pA + pB; }
                SCORE1(sc0, q0) SCORE1(sc1, q1) SCORE1(sc2, q2) SCORE1(sc3, q3)
#undef SCORE1

#pragma unroll
                for (int d = 8; d >= 1; d >>= 1) {
                    sc0 += __shfl_xor_sync(F, sc0, d);
                    sc1 += __shfl_xor_sync(F, sc1, d);
                    sc2 += __shfl_xor_sync(F, sc2, d);
                    sc3 += __shfl_xor_sync(F, sc3, d);
                }

                float e0 = __expf(sc0);
                float e1 = (j + 1 < cnt) ? __expf(sc1) : 0.f;
                float e2 = (j + 2 < cnt) ? __expf(sc2) : 0.f;
                float e3 = (j + 3 < cnt) ? __expf(sc3) : 0.f;

                S0 = fmaf(e0, q0.x, S0); S1 = fmaf(e0, q0.y, S1);
                S0 = fmaf(e1, q1.x, S0); S1 = fmaf(e1, q1.y, S1);
                S0 = fmaf(e2, q2.x, S0); S1 = fmaf(e2, q2.y, S1);
                S0 = fmaf(e3, q3.x, S0); S1 = fmaf(e3, q3.y, S1);
                den += e0 + e1 + e2 + e3;
            }
        }

        float inv = 0.25f / (den + 1e-16f);
        outv.x = fmaf(fmaf(S1, wl1.x, fmaf(S0, wl0.x, den * blv.x)), inv, outv.x);
        outv.y = fmaf(fmaf(S1, wl1.y, fmaf(S0, wl0.y, den * blv.y)), inv, outv.y);
        outv.z = fmaf(fmaf(S1, wl1.z, fmaf(S0, wl0.z, den * blv.z)), inv, outv.z);
        outv.w = fmaf(fmaf(S1, wl1.w, fmaf(S0, wl0.w, den * blv.w)), inv, outv.w);
    }

    outv.x += __shfl_xor_sync(F, outv.x, 16);
    outv.y += __shfl_xor_sync(F, outv.y, 16);
    outv.z += __shfl_xor_sync(F, outv.z, 16);
    outv.w += __shfl_xor_sync(F, outv.w, 16);

    if (lane < 16) {
        int c = lane * 4;
        outv.x += 0.5f * (bias[c + 0] + bias[64 + c + 0]);
        outv.y += 0.5f * (bias[c + 1] + bias[64 + c + 1]);
        outv.z += 0.5f * (bias[c + 2] + bias[64 + c + 2]);
        outv.w += 0.5f * (bias[c + 3] + bias[64 + c + 3]);
        outv.x = outv.x > 0.f ? outv.x : 0.f;
        outv.y = outv.y > 0.f ? outv.y : 0.f;
        outv.z = outv.z > 0.f ? outv.z : 0.f;
        outv.w = outv.w > 0.f ? outv.w : 0.f;
        *(float4*)&h[(size_t)node * 64 + c] = outv;
    }
}

// ---------------------------------------------------------------------------
// Layer-2 transforms: 4 GEMMs via grid.y. xl (y even) -> fp16, xr (y odd) -> fp32
__global__ void __launch_bounds__(128)
transform64_all_kernel(const float* __restrict__ X,
                       const float* __restrict__ Wl,
                       const float* __restrict__ bl,
                       const float* __restrict__ Wr,
                       const float* __restrict__ br,
                       __half* __restrict__ xlh,     // [2][NMAX*HD]
                       float* __restrict__ xrf,      // [2][NMAX*HD]
                       int n) {
    __shared__ float sW[64 * 128];
    __shared__ float sX[32 * 68];

    int y = blockIdx.y;
    int r = y >> 1;
    bool is_xl = (y & 1) == 0;
    const float* W = is_xl ? (Wl + r * 64 * HD) : (Wr + r * 64 * HD);
    const float* b = is_xl ? (bl + r * HD)      : (br + r * HD);

    int tx = threadIdx.x;
    for (int idx = tx * 4; idx < 64 * 128; idx += 128 * 4)
        *(float4*)&sW[idx] = *(const float4*)&W[idx];

    int node0 = blockIdx.x * 32;
    for (int idx = tx; idx < 512; idx += 128) {
        int rr = idx >> 4;
        int c4 = idx & 15;
        float4 v = make_float4(0.f, 0.f, 0.f, 0.f);
        if (node0 + rr < n)
            v = *(const float4*)&X[(size_t)(node0 + rr) * 64 + c4 * 4];
        *(float4*)&sX[rr * 68 + c4 * 4] = v;
    }
    __syncthreads();

    int cg = tx & 15;
    int ng = tx >> 4;

    float acc[4][8];
#pragma unroll
    for (int m = 0; m < 4; m++)
#pragma unroll
        for (int j = 0; j < 8; j++) acc[m][j] = b[cg * 8 + j];

    for (int k = 0; k < 64; k += 4) {
        float4 xv[4];
#pragma unroll
        for (int m = 0; m < 4; m++)
            xv[m] = *(const float4*)&sX[(ng * 4 + m) * 68 + k];
#pragma unroll
        for (int kk = 0; kk < 4; kk++) {
            float4 w0 = *(const float4*)&sW[(k + kk) * 128 + cg * 8];
            float4 w1 = *(const float4*)&sW[(k + kk) * 128 + cg * 8 + 4];
#pragma unroll
            for (int m = 0; m < 4; m++) {
                float xs = (kk == 0) ? xv[m].x : (kk == 1) ? xv[m].y
                         : (kk == 2) ? xv[m].z : xv[m].w;
                acc[m][0] = fmaf(xs, w0.x, acc[m][0]);
                acc[m][1] = fmaf(xs, w0.y, acc[m][1]);
                acc[m][2] = fmaf(xs, w0.z, acc[m][2]);
                acc[m][3] = fmaf(xs, w0.w, acc[m][3]);
                acc[m][4] = fmaf(xs, w1.x, acc[m][4]);
                acc[m][5] = fmaf(xs, w1.y, acc[m][5]);
                acc[m][6] = fmaf(xs, w1.z, acc[m][6]);
                acc[m][7] = fmaf(xs, w1.w, acc[m][7]);
            }
        }
    }

    if (is_xl) {
        __half* Y = xlh + (size_t)r * NMAX * HD;
#pragma unroll
        for (int m = 0; m < 4; m++) {
            int node = node0 + ng * 4 + m;
            if (node < n) {
                __half2 p0 = __float22half2_rn(make_float2(acc[m][0], acc[m][1]));
                __half2 p1 = __float22half2_rn(make_float2(acc[m][2], acc[m][3]));
                __half2 p2 = __float22half2_rn(make_float2(acc[m][4], acc[m][5]));
                __half2 p3 = __float22half2_rn(make_float2(acc[m][6], acc[m][7]));
                uint4 pk;
                pk.x = *(unsigned*)&p0; pk.y = *(unsigned*)&p1;
                pk.z = *(unsigned*)&p2; pk.w = *(unsigned*)&p3;
                *(uint4*)&Y[(size_t)node * HD + cg * 8] = pk;
            }
        }
    } else {
        float* Y = xrf + (size_t)r * NMAX * HD;
#pragma unroll
        for (int m = 0; m < 4; m++) {
            int node = node0 + ng * 4 + m;
            if (node < n) {
                *(float4*)&Y[(size_t)node * HD + cg * 8] =
                    make_float4(acc[m][0], acc[m][1], acc[m][2], acc[m][3]);
                *(float4*)&Y[(size_t)node * HD + cg * 8 + 4] =
                    make_float4(acc[m][4], acc[m][5], acc[m][6], acc[m][7]);
            }
        }
    }
}

// ---------------------------------------------------------------------------
// Layer-2 fused pull: per warp = node, both relations. fp16 xl gathers (8 B).
__global__ void __launch_bounds__(128, 8)
layer2_fused_kernel(const int* __restrict__ rowptr,
                    const int* __restrict__ csrc,
                    const __half* __restrict__ xlh,   // [2][NMAX*HD]
                    const float* __restrict__ xrf,    // [2][NMAX*HD]
                    const float* __restrict__ att,
                    const float* __restrict__ bias,
                    float* __restrict__ out, int n) {
    const unsigned F = 0xffffffffu;
    int node = (blockIdx.x * blockDim.x + threadIdx.x) >> 5;
    if (node >= n) return;
    int lane = threadIdx.x & 31;

    float4 outv = make_float4(0.f, 0.f, 0.f, 0.f);

#pragma unroll 1
    for (int r = 0; r < 2; r++) {
        const __half* xl = xlh + (size_t)r * NMAX * HD;
        const float*  xr = xrf + (size_t)r * NMAX * HD;
        const float4 a4  = *(const float4*)&att[r * HD + lane * 4];
        const float4 xrv = *(const float4*)&xr[(size_t)node * HD + lane * 4];

        const int* rp = rowptr + r * (NMAX + 1);
        const int* cs = csrc   + r * EMAX;
        int beg = rp[node];
        int end = rp[node + 1];

        float4 ns = make_float4(0.f, 0.f, 0.f, 0.f);
        float den = 0.f;

        for (int bse = beg; bse < end; bse += 32) {
            int cnt = end - bse; if (cnt > 32) cnt = 32;
            int ld = bse + lane; if (ld >= end) ld = end - 1;
            int sv = cs[ld];

            for (int j = 0; j < cnt; j += 4) {
                int i1 = (j + 1 < cnt) ? j + 1 : j;
                int i2 = (j + 2 < cnt) ? j + 2 : j;
                int i3 = (j + 3 < cnt) ? j + 3 : j;
                int s0 = __shfl_sync(F, sv, j);
                int s1 = __shfl_sync(F, sv, i1);
                int s2 = __shfl_sync(F, sv, i2);
                int s3 = __shfl_sync(F, sv, i3);

                // 8 B fp16 gathers
                uint2 r0 = *(const uint2*)&xl[(size_t)s0 * HD + lane * 4];
                uint2 r1 = *(const uint2*)&xl[(size_t)s1 * HD + lane * 4];
                uint2 r2 = *(const uint2*)&xl[(size_t)s2 * HD + lane * 4];
                uint2 r3 = *(const uint2*)&xl[(size_t)s3 * HD + lane * 4];

                float4 a0, a1, a2, a3;
#define UNPACK(a, rr) { \
    float2 lo = __half22float2(*(__half2*)&rr.x); \
    float2 hi = __half22float2(*(__half2*)&rr.y); \
    a = make_float4(lo.x, lo.y, hi.x, hi.y); }
                UNPACK(a0, r0) UNPACK(a1, r1) UNPACK(a2, r2) UNPACK(a3, r3)
#undef UNPACK

                float sc0, sc1, sc2, sc3;
#define SCORE(sc, a) { \
    float v0 = a.x + xrv.x; \
    float v1 = a.y + xrv.y; \
    float v2 = a.z + xrv.z; \
    float v3 = a.w + xrv.w; \
    v0 = v0 > 0.f ? v0 : 0.2f * v0; \
    v1 = v1 > 0.f ? v1 : 0.2f * v1; \
    v2 = v2 > 0.f ? v2 : 0.2f * v2; \
    v3 = v3 > 0.f ? v3 : 0.2f * v3; \
    float pA = v0 * a4.x; \
    float pB = v1 * a4.y; \
    pA = fmaf(v2, a4.z, pA); \
    pB = fmaf(v3, a4.w, pB); \
    sc = pA + pB; }
                SCORE(sc0, a0) SCORE(sc1, a1) SCORE(sc2, a2) SCORE(sc3, a3)
#undef SCORE

#pragma unroll
                for (int d = 8; d >= 1; d >>= 1) {
                    sc0 += __shfl_xor_sync(F, sc0, d);
                    sc1 += __shfl_xor_sync(F, sc1, d);
                    sc2 += __shfl_xor_sync(F, sc2, d);
                    sc3 += __shfl_xor_sync(F, sc3, d);
                }

                float e0 = __expf(sc0);
                float e1 = (j + 1 < cnt) ? __expf(sc1) : 0.f;
                float e2 = (j + 2 < cnt) ? __expf(sc2) : 0.f;
                float e3 = (j + 3 < cnt) ? __expf(sc3) : 0.f;

                ns.x = fmaf(e0, a0.x, ns.x); ns.y = fmaf(e0, a0.y, ns.y);
                ns.z = fmaf(e0, a0.z, ns.z); ns.w = fmaf(e0, a0.w, ns.w);
                ns.x = fmaf(e1, a1.x, ns.x); ns.y = fmaf(e1, a1.y, ns.y);
                ns.z = fmaf(e1, a1.z, ns.z); ns.w = fmaf(e1, a1.w, ns.w);
                ns.x = fmaf(e2, a2.x, ns.x); ns.y = fmaf(e2, a2.y, ns.y);
                ns.z = fmaf(e2, a2.z, ns.z); ns.w = fmaf(e2, a2.w, ns.w);
                ns.x = fmaf(e3, a3.x, ns.x); ns.y = fmaf(e3, a3.y, ns.y);
                ns.z = fmaf(e3, a3.z, ns.z); ns.w = fmaf(e3, a3.w, ns.w);
                den += e0 + e1 + e2 + e3;
            }
        }

        float inv = 0.25f / (den + 1e-16f);
        outv.x = fmaf(ns.x, inv, outv.x);
        outv.y = fmaf(ns.y, inv, outv.y);
        outv.z = fmaf(ns.z, inv, outv.z);
        outv.w = fmaf(ns.w, inv, outv.w);
    }

    outv.x += __shfl_xor_sync(F, outv.x, 16);
    outv.y += __shfl_xor_sync(F, outv.y, 16);
    outv.z += __shfl_xor_sync(F, outv.z, 16);
    outv.w += __shfl_xor_sync(F, outv.w, 16);

    if (lane < 16) {
        int c = lane * 4;
        outv.x += 0.5f * (bias[c + 0] + bias[64 + c + 0]);
        outv.y += 0.5f * (bias[c + 1] + bias[64 + c + 1]);
        outv.z += 0.5f * (bias[c + 2] + bias[64 + c + 2]);
        outv.w += 0.5f * (bias[c + 3] + bias[64 + c + 3]);
        *(float4*)&out[(size_t)node * 64 + c] = outv;
    }
}

// ---------------------------------------------------------------------------
extern "C" void kernel_launch(void* const* d_in, const int* in_sizes, int n_in,
                              void* d_out, int out_size) {
    const float* x       = (const float*)d_in[0];
    const int*   e_adj   = (const int*)  d_in[1];
    const int*   e_ray   = (const int*)  d_in[2];
    const float* l1_Wl   = (const float*)d_in[3];
    const float* l1_bl   = (const float*)d_in[4];
    const float* l1_Wr   = (const float*)d_in[5];
    const float* l1_br   = (const float*)d_in[6];
    const float* l1_att  = (const float*)d_in[7];
    const float* l1_bias = (const float*)d_in[8];
    const float* l2_Wl   = (const float*)d_in[9];
    const float* l2_bl   = (const float*)d_in[10];
    const float* l2_Wr   = (const float*)d_in[11];
    const float* l2_br   = (const float*)d_in[12];
    const float* l2_att  = (const float*)d_in[13];
    const float* l2_bias = (const float*)d_in[14];

    const int N = in_sizes[0] / 2;
    const int E = in_sizes[1] / 2;

    __half* xlh; float *xrf, *h;
    int *rowptr, *cursor, *csrc;
    cudaGetSymbolAddress((void**)&xlh,    g_xlh);
    cudaGetSymbolAddress((void**)&xrf,    g_xr);
    cudaGetSymbolAddress((void**)&h,      g_h);
    cudaGetSymbolAddress((void**)&rowptr, g_rowptr);
    cudaGetSymbolAddress((void**)&cursor, g_cursor);
    cudaGetSymbolAddress((void**)&csrc,   g_csrc);

    const int ZB = 256;
    const int EB = (E + ZB - 1) / ZB;
    const int PULL_BLOCKS = (N + 3) / 4;   // 4 warps per 128-thread block

    // ----- CSR build (cursors pre-zeroed: load-time init + tail kernel) -----
    {
        dim3 g(EB, 2);
        hist2_kernel<<<g, ZB>>>(e_adj + E, e_ray + E, cursor, E);
    }
    scan2_kernel<<<2, 1024>>>(cursor, rowptr, N);
    {
        dim3 g(EB, 2);
        scatter2_kernel<<<g, ZB>>>(e_adj, e_ray, cursor, csrc, E);
    }

    // ----- Layer 1 (launch #4 -> ncu capture slot) -----
    layer1_fused_kernel<<<PULL_BLOCKS, 128>>>(
        rowptr, csrc, x, l1_Wl, l1_bl, l1_Wr, l1_br, l1_att, l1_bias, h, N);

    // ----- Layer 2 -----
    {
        dim3 g((N + 31) / 32, 4);
        transform64_all_kernel<<<g, 128>>>(h, l2_Wl, l2_bl, l2_Wr, l2_br,
                                           xlh, xrf, N);
    }
    layer2_fused_kernel<<<PULL_BLOCKS, 128>>>(
        rowptr, csrc, xlh, xrf, l2_att, l2_bias, (float*)d_out, N);

    // ----- Tail: re-zero cursors for the next call -----
    zero2_kernel<<<(N + ZB - 1) / ZB, ZB>>>(cursor, N);
}